// round 3
// baseline (speedup 1.0000x reference)
#include <cuda_runtime.h>
#include <cuda_fp16.h>
#include <cstdint>

// ---------------------------------------------------------------------------
// Problem constants
// ---------------------------------------------------------------------------
#define N_ROWS 100000
#define HID    512
#define D_IN   64
#define PH     16
#define NOBS   50000
#define K1     1024      // PH*D
#define K2     512       // HID
#define H3     1536      // 3*HID
#define MTILES ((NOBS + 127) / 128)   // 391

// ---------------------------------------------------------------------------
// Scratch (__device__ globals — sanctioned scratch path, no runtime allocs)
// ---------------------------------------------------------------------------
__device__ __half g_Wih_h[(size_t)H3 * K1];     //  3 MB
__device__ __half g_Whh_h[(size_t)H3 * K2];     //  1.5 MB
__device__ __half g_gruin[(size_t)NOBS * K1];   // 100 MB
__device__ __half g_hgat [(size_t)NOBS * K2];   //  50 MB
__device__ __half g_gi   [(size_t)NOBS * H3];   // 150 MB
__device__ __half g_gh   [(size_t)NOBS * H3];   // 150 MB
__device__ float  g_loss;

// ---------------------------------------------------------------------------
// Helpers
// ---------------------------------------------------------------------------
__device__ __forceinline__ uint32_t smem_to_u32(const void* smem_ptr) {
    uint32_t addr;
    asm("{ .reg .u64 tmp; cvta.to.shared.u64 tmp, %1; cvt.u32.u64 %0, tmp; }"
        : "=r"(addr) : "l"(smem_ptr));
    return addr;
}

__device__ __forceinline__ void cp_async16(uint32_t dst, const void* src, int src_bytes) {
    asm volatile("cp.async.cg.shared.global [%0], [%1], 16, %2;"
                 :: "r"(dst), "l"(src), "r"(src_bytes));
}
#define CP_ASYNC_COMMIT() asm volatile("cp.async.commit_group;" ::: "memory")
#define CP_ASYNC_WAIT_1() asm volatile("cp.async.wait_group 1;" ::: "memory")

#define LDMATRIX_X4(r0, r1, r2, r3, addr) \
    asm volatile("ldmatrix.sync.aligned.m8n8.x4.shared.b16 {%0,%1,%2,%3}, [%4];" \
                 : "=r"(r0), "=r"(r1), "=r"(r2), "=r"(r3) : "r"(addr))

#define MMA_16816(d, a, b) \
    asm volatile("mma.sync.aligned.m16n8k16.row.col.f32.f16.f16.f32 " \
                 "{%0,%1,%2,%3}, {%4,%5,%6,%7}, {%8,%9}, {%0,%1,%2,%3};" \
                 : "+f"((d)[0]), "+f"((d)[1]), "+f"((d)[2]), "+f"((d)[3]) \
                 : "r"((a)[0]), "r"((a)[1]), "r"((a)[2]), "r"((a)[3]), \
                   "r"((b)[0]), "r"((b)[1]))

// ---------------------------------------------------------------------------
// 1. Weight convert + loss zero
// ---------------------------------------------------------------------------
__global__ void convert_weights_kernel(const float* __restrict__ wih,
                                       const float* __restrict__ whh) {
    const int n1 = H3 * K1;
    const int n2 = H3 * K2;
    for (int i = blockIdx.x * blockDim.x + threadIdx.x; i < n1 + n2;
         i += gridDim.x * blockDim.x) {
        if (i < n1) g_Wih_h[i] = __float2half_rn(wih[i]);
        else        g_Whh_h[i - n1] = __float2half_rn(whh[i - n1]);
    }
    if (blockIdx.x == 0 && threadIdx.x == 0) g_loss = 0.0f;
}

// ---------------------------------------------------------------------------
// 2. Prep: loss + feats einsum + relu*mask -> g_gruin (fp16)
// ---------------------------------------------------------------------------
__global__ void __launch_bounds__(256) prep_kernel(
    const float* __restrict__ p, const float* __restrict__ X,
    const float* __restrict__ M, const int* __restrict__ iobs,
    const float* __restrict__ wprep, const float* __restrict__ bprep) {
    __shared__ float sw[D_IN * 64];   // [d][f*16+j]
    __shared__ float sb[D_IN * PH];
    __shared__ float sred[256];

    for (int i = threadIdx.x; i < D_IN * 64; i += 256) sw[i] = wprep[i];
    for (int i = threadIdx.x; i < D_IN * PH; i += 256) sb[i] = bprep[i];
    __syncthreads();

    const int d   = threadIdx.x & 63;
    const int sub = threadIdx.x >> 6;   // 0..3
    const int base = blockIdx.x * 32;
    float lacc = 0.0f;

    for (int rr = sub; rr < 32; rr += 4) {
        const int r = base + rr;
        if (r >= NOBS) continue;
        const int i = iobs[r];
        const float mean = p[(size_t)i * 128 + d];
        const float var  = fabsf(p[(size_t)i * 128 + 64 + d]) + 1e-6f;
        const float x    = X[(size_t)r * 64 + d];
        const float m    = M[(size_t)r * 64 + d];
        const float rsv  = rsqrtf(var);
        const float err  = (x - mean) * rsv;
        lacc += 0.5f * (err * err + logf(var)) * m;

        const float* w = sw + d * 64;
        const float* b = sb + d * 16;
        __half2 hv[8];
        #pragma unroll
        for (int j = 0; j < 16; j += 2) {
            float v0 = b[j];
            v0 = fmaf(x, w[j], v0);
            v0 = fmaf(mean, w[16 + j], v0);
            v0 = fmaf(var,  w[32 + j], v0);
            v0 = fmaf(err,  w[48 + j], v0);
            float v1 = b[j + 1];
            v1 = fmaf(x, w[j + 1], v1);
            v1 = fmaf(mean, w[16 + j + 1], v1);
            v1 = fmaf(var,  w[32 + j + 1], v1);
            v1 = fmaf(err,  w[48 + j + 1], v1);
            v0 = fmaxf(v0, 0.0f) * m;
            v1 = fmaxf(v1, 0.0f) * m;
            hv[j >> 1] = __floats2half2_rn(v0, v1);
        }
        uint4* dst = reinterpret_cast<uint4*>(&g_gruin[(size_t)r * K1 + d * 16]);
        dst[0] = *reinterpret_cast<uint4*>(&hv[0]);
        dst[1] = *reinterpret_cast<uint4*>(&hv[4]);
    }

    sred[threadIdx.x] = lacc;
    __syncthreads();
    for (int s = 128; s > 0; s >>= 1) {
        if (threadIdx.x < s) sred[threadIdx.x] += sred[threadIdx.x + s];
        __syncthreads();
    }
    if (threadIdx.x == 0) atomicAdd(&g_loss, sred[0]);
}

// ---------------------------------------------------------------------------
// 3. Gather h[i_obs] -> fp16
// ---------------------------------------------------------------------------
__global__ void gather_h_kernel(const float* __restrict__ h,
                                const int* __restrict__ iobs) {
    const int total = NOBS * (HID / 2);
    int idx = blockIdx.x * blockDim.x + threadIdx.x;
    if (idx >= total) return;
    const int r = idx >> 8;          // HID/2 = 256
    const int c = idx & 255;
    const int i = iobs[r];
    float2 v = *reinterpret_cast<const float2*>(&h[(size_t)i * HID + c * 2]);
    reinterpret_cast<__half2*>(g_hgat)[idx] = __floats2half2_rn(v.x, v.y);
}

// ---------------------------------------------------------------------------
// 4. HMMA GEMM: C[M,1536](fp16) = A[M,K](fp16) @ B[1536,K](fp16)^T
//    BM=128, BN=128, BK=32, 2-stage cp.async (wait -> compute -> sync ->
//    prefetch-into-freed-buffer), 256 thr (8 warps, 4m x 2n), warp tile
//    32x64, mma.sync m16n8k16, padded 80B smem rows for conflict-free
//    ldmatrix.
// ---------------------------------------------------------------------------
// smem layout (bytes): A stage0 [0,10240) stage1 [10240,20480)
//                      B stage0 [20480,30720) stage1 [30720,40960)
#define SM_A_STAGE 10240
#define SM_B_BASE  20480

__device__ __forceinline__ void load_stage(uint32_t sm, int buf,
                                           const __half* __restrict__ A,
                                           const __half* __restrict__ B,
                                           int m0, int n0, int K, int kc, int tid) {
    #pragma unroll
    for (int it = 0; it < 4; it++) {
        const int c = tid + it * 256;           // 0..1023
        const int cc = c & 511;
        const int row = cc >> 2, ch = cc & 3;   // 128 rows x 4 x 16B
        if (c < 512) {  // A
            const int rg = m0 + row;
            const int rc = rg < NOBS ? rg : (NOBS - 1);
            const void* src = A + (size_t)rc * K + kc * 32 + ch * 8;
            cp_async16(sm + buf * SM_A_STAGE + row * 80 + ch * 16, src,
                       rg < NOBS ? 16 : 0);
        } else {        // B (always in range)
            const void* src = B + (size_t)(n0 + row) * K + kc * 32 + ch * 8;
            cp_async16(sm + SM_B_BASE + buf * SM_A_STAGE + row * 80 + ch * 16,
                       src, 16);
        }
    }
}

__global__ void __launch_bounds__(256, 2) gemm_hmma_kernel(
    const __half* __restrict__ A, const __half* __restrict__ B,
    __half* __restrict__ C, int K) {
    __shared__ __align__(128) char smem[40960];
    const uint32_t sm = smem_to_u32(smem);

    const int tid  = threadIdx.x;
    const int lane = tid & 31;
    const int wid  = tid >> 5;
    const int warp_m = wid & 3;     // 4 m-warps, 32 rows each
    const int warp_n = wid >> 2;    // 2 n-warps, 64 cols each

    const int n0 = blockIdx.x * 128;
    const int m0 = blockIdx.y * 128;
    const int nk = K >> 5;

    // per-lane ldmatrix base offsets (bytes) within a stage
    const uint32_t lrow = lane & 15;
    const uint32_t lcol = (lane >> 4) << 4;   // 0 or 16 bytes (8 halfs)
    const uint32_t a_off = (warp_m * 32 + lrow) * 80 + lcol;
    const uint32_t b_off = (warp_n * 64 + lrow) * 80 + lcol;

    float acc[2][8][4];
    #pragma unroll
    for (int mt = 0; mt < 2; mt++)
        #pragma unroll
        for (int nt = 0; nt < 8; nt++)
            #pragma unroll
            for (int e = 0; e < 4; e++) acc[mt][nt][e] = 0.0f;

    // prologue: chunk 0 -> buf 0, chunk 1 -> buf 1
    load_stage(sm, 0, A, B, m0, n0, K, 0, tid);
    CP_ASYNC_COMMIT();
    load_stage(sm, 1, A, B, m0, n0, K, 1, tid);
    CP_ASYNC_COMMIT();

    for (int kc = 0; kc < nk; kc++) {
        const int buf = kc & 1;
        CP_ASYNC_WAIT_1();          // chunk kc landed (older group retires first)
        __syncthreads();

        const uint32_t sA = sm + buf * SM_A_STAGE;
        const uint32_t sB = sm + SM_B_BASE + buf * SM_A_STAGE;

        #pragma unroll
        for (int ks = 0; ks < 2; ks++) {
            const uint32_t k0b = ks * 32;      // 16 halfs = 32 bytes
            uint32_t a[2][4];
            LDMATRIX_X4(a[0][0], a[0][1], a[0][2], a[0][3], sA + a_off + k0b);
            LDMATRIX_X4(a[1][0], a[1][1], a[1][2], a[1][3], sA + a_off + 1280 + k0b);
            uint32_t b[8][2];
            #pragma unroll
            for (int nb = 0; nb < 4; nb++) {
                uint32_t r0, r1, r2, r3;
                LDMATRIX_X4(r0, r1, r2, r3, sB + b_off + nb * 1280 + k0b);
                b[2 * nb][0] = r0; b[2 * nb][1] = r2;
                b[2 * nb + 1][0] = r1; b[2 * nb + 1][1] = r3;
            }
            #pragma unroll
            for (int mt = 0; mt < 2; mt++)
                #pragma unroll
                for (int nt = 0; nt < 8; nt++)
                    MMA_16816(acc[mt][nt], a[mt], b[nt]);
        }
        __syncthreads();            // all warps done reading buf

        // prefetch chunk kc+2 into the buffer just freed (overlaps with the
        // compute of chunk kc+1 next iteration)
        if (kc + 2 < nk) load_stage(sm, buf, A, B, m0, n0, K, kc + 2, tid);
        CP_ASYNC_COMMIT();          // empty group when past the end keeps
                                    // wait_group accounting exact
    }

    // epilogue: fp32 -> fp16, store
    #pragma unroll
    for (int mt = 0; mt < 2; mt++) {
        const int r0 = m0 + warp_m * 32 + mt * 16 + (lane >> 2);
        #pragma unroll
        for (int nt = 0; nt < 8; nt++) {
            const int col = n0 + warp_n * 64 + nt * 8 + (lane & 3) * 2;
            if (r0 < NOBS)
                *reinterpret_cast<__half2*>(&C[(size_t)r0 * H3 + col]) =
                    __floats2half2_rn(acc[mt][nt][0], acc[mt][nt][1]);
            if (r0 + 8 < NOBS)
                *reinterpret_cast<__half2*>(&C[(size_t)(r0 + 8) * H3 + col]) =
                    __floats2half2_rn(acc[mt][nt][2], acc[mt][nt][3]);
        }
    }
}

// ---------------------------------------------------------------------------
// 5. Gate combine + scatter (last occurrence of each index wins)
// ---------------------------------------------------------------------------
__global__ void __launch_bounds__(128) combine_kernel(
    const int* __restrict__ iobs, const float* __restrict__ h,
    const float* __restrict__ bih, const float* __restrict__ bhh,
    float* __restrict__ out) {
    const int r = blockIdx.x;
    const int i = iobs[r];
    if (r + 1 < NOBS && iobs[r + 1] == i) return;   // not last occurrence

    const size_t gbase = (size_t)r * H3;
    for (int j = threadIdx.x; j < HID; j += 128) {
        const float ir  = __half2float(g_gi[gbase + j])         + bih[j];
        const float iz  = __half2float(g_gi[gbase + 512 + j])   + bih[512 + j];
        const float in_ = __half2float(g_gi[gbase + 1024 + j])  + bih[1024 + j];
        const float hr  = __half2float(g_gh[gbase + j])         + bhh[j];
        const float hz  = __half2float(g_gh[gbase + 512 + j])   + bhh[512 + j];
        const float hn  = __half2float(g_gh[gbase + 1024 + j])  + bhh[1024 + j];
        const float rg = 1.0f / (1.0f + expf(-(ir + hr)));
        const float zg = 1.0f / (1.0f + expf(-(iz + hz)));
        const float nn = tanhf(in_ + rg * hn);
        const float hp = h[(size_t)i * HID + j];
        out[(size_t)i * HID + j] = (1.0f - zg) * nn + zg * hp;
    }
}

// ---------------------------------------------------------------------------
// 6. Loss store
// ---------------------------------------------------------------------------
__global__ void write_loss_kernel(float* __restrict__ out) {
    out[(size_t)N_ROWS * HID] = g_loss;
}

// ---------------------------------------------------------------------------
// Launch
// ---------------------------------------------------------------------------
extern "C" void kernel_launch(void* const* d_in, const int* in_sizes, int n_in,
                              void* d_out, int out_size) {
    const float* h     = (const float*)d_in[0];
    const float* p     = (const float*)d_in[1];
    const float* X     = (const float*)d_in[2];
    const float* M     = (const float*)d_in[3];
    const int*   iobs  = (const int*)  d_in[4];
    const float* wprep = (const float*)d_in[5];
    const float* bprep = (const float*)d_in[6];
    const float* wih   = (const float*)d_in[7];
    const float* whh   = (const float*)d_in[8];
    const float* bih   = (const float*)d_in[9];
    const float* bhh   = (const float*)d_in[10];
    float* out = (float*)d_out;

    // 1. convert weights to fp16, zero loss accumulator
    convert_weights_kernel<<<512, 256>>>(wih, whh);

    // 2. out[:N*HID] = h
    cudaMemcpyAsync(out, h, (size_t)N_ROWS * HID * sizeof(float),
                    cudaMemcpyDeviceToDevice);

    // 3. prep: loss + gru_in (fp16)
    prep_kernel<<<(NOBS + 31) / 32, 256>>>(p, X, M, iobs, wprep, bprep);

    // 4. gather h[i_obs] -> fp16
    gather_h_kernel<<<(NOBS * (HID / 2) + 255) / 256, 256>>>(h, iobs);

    // device pointers to the scratch symbols for GEMM args
    __half *d_gruin, *d_hgat, *d_gi, *d_gh, *d_wih, *d_whh;
    cudaGetSymbolAddress((void**)&d_gruin, g_gruin);
    cudaGetSymbolAddress((void**)&d_hgat,  g_hgat);
    cudaGetSymbolAddress((void**)&d_gi,    g_gi);
    cudaGetSymbolAddress((void**)&d_gh,    g_gh);
    cudaGetSymbolAddress((void**)&d_wih,   g_Wih_h);
    cudaGetSymbolAddress((void**)&d_whh,   g_Whh_h);

    // 5. gi = gru_in @ Wih^T   (M=50000, N=1536, K=1024)
    gemm_hmma_kernel<<<dim3(12, MTILES), 256>>>(d_gruin, d_wih, d_gi, K1);

    // 6. gh = h_gat @ Whh^T    (M=50000, N=1536, K=512)
    gemm_hmma_kernel<<<dim3(12, MTILES), 256>>>(d_hgat, d_whh, d_gh, K2);

    // 7. gates + scatter (last-wins)
    combine_kernel<<<NOBS, 128>>>(iobs, h, bih, bhh, out);

    // 8. loss
    if (out_size > N_ROWS * HID)
        write_loss_kernel<<<1, 1>>>(out);
}

// round 4
// speedup vs baseline: 1.0758x; 1.0758x over previous
#include <cuda_runtime.h>
#include <cuda_fp16.h>
#include <cstdint>

// ---------------------------------------------------------------------------
// Problem constants
// ---------------------------------------------------------------------------
#define N_ROWS 100000
#define HID    512
#define D_IN   64
#define PH     16
#define NOBS   50000
#define K1     1024      // PH*D
#define K2     512       // HID
#define H3     1536      // 3*HID
#define MTILES ((NOBS + 127) / 128)   // 391

// ---------------------------------------------------------------------------
// Scratch (__device__ globals — sanctioned scratch path, no runtime allocs)
// ---------------------------------------------------------------------------
__device__ __half g_Wih_h[(size_t)H3 * K1];     //  3 MB
__device__ __half g_Whh_h[(size_t)H3 * K2];     //  1.5 MB
__device__ __half g_gruin[(size_t)NOBS * K1];   // 100 MB
__device__ __half g_hgat [(size_t)NOBS * K2];   //  50 MB
__device__ __half g_gi   [(size_t)NOBS * H3];   // 150 MB
__device__ __half g_gh   [(size_t)NOBS * H3];   // 150 MB
__device__ float  g_loss;

// ---------------------------------------------------------------------------
// Helpers
// ---------------------------------------------------------------------------
__device__ __forceinline__ uint32_t smem_to_u32(const void* smem_ptr) {
    uint32_t addr;
    asm("{ .reg .u64 tmp; cvta.to.shared.u64 tmp, %1; cvt.u32.u64 %0, tmp; }"
        : "=r"(addr) : "l"(smem_ptr));
    return addr;
}

__device__ __forceinline__ void cp_async16(uint32_t dst, const void* src, int src_bytes) {
    asm volatile("cp.async.cg.shared.global [%0], [%1], 16, %2;"
                 :: "r"(dst), "l"(src), "r"(src_bytes));
}
#define CP_ASYNC_COMMIT() asm volatile("cp.async.commit_group;" ::: "memory")
#define CP_ASYNC_WAIT_2() asm volatile("cp.async.wait_group 2;" ::: "memory")

#define LDMATRIX_X4(r0, r1, r2, r3, addr) \
    asm volatile("ldmatrix.sync.aligned.m8n8.x4.shared.b16 {%0,%1,%2,%3}, [%4];" \
                 : "=r"(r0), "=r"(r1), "=r"(r2), "=r"(r3) : "r"(addr))

#define MMA_16816(d, a, b) \
    asm volatile("mma.sync.aligned.m16n8k16.row.col.f32.f16.f16.f32 " \
                 "{%0,%1,%2,%3}, {%4,%5,%6,%7}, {%8,%9}, {%0,%1,%2,%3};" \
                 : "+f"((d)[0]), "+f"((d)[1]), "+f"((d)[2]), "+f"((d)[3]) \
                 : "r"((a)[0]), "r"((a)[1]), "r"((a)[2]), "r"((a)[3]), \
                   "r"((b)[0]), "r"((b)[1]))

// ---------------------------------------------------------------------------
// 1. Weight convert + loss zero
// ---------------------------------------------------------------------------
__global__ void convert_weights_kernel(const float* __restrict__ wih,
                                       const float* __restrict__ whh) {
    const int n1 = H3 * K1;
    const int n2 = H3 * K2;
    for (int i = blockIdx.x * blockDim.x + threadIdx.x; i < n1 + n2;
         i += gridDim.x * blockDim.x) {
        if (i < n1) g_Wih_h[i] = __float2half_rn(wih[i]);
        else        g_Whh_h[i - n1] = __float2half_rn(whh[i - n1]);
    }
    if (blockIdx.x == 0 && threadIdx.x == 0) g_loss = 0.0f;
}

// ---------------------------------------------------------------------------
// 2. Prep: loss + feats einsum + relu*mask -> g_gruin (fp16)
// ---------------------------------------------------------------------------
__global__ void __launch_bounds__(256) prep_kernel(
    const float* __restrict__ p, const float* __restrict__ X,
    const float* __restrict__ M, const int* __restrict__ iobs,
    const float* __restrict__ wprep, const float* __restrict__ bprep) {
    __shared__ float sw[D_IN * 64];   // [d][f*16+j]
    __shared__ float sb[D_IN * PH];
    __shared__ float sred[256];

    for (int i = threadIdx.x; i < D_IN * 64; i += 256) sw[i] = wprep[i];
    for (int i = threadIdx.x; i < D_IN * PH; i += 256) sb[i] = bprep[i];
    __syncthreads();

    const int d   = threadIdx.x & 63;
    const int sub = threadIdx.x >> 6;   // 0..3
    const int base = blockIdx.x * 32;
    float lacc = 0.0f;

    for (int rr = sub; rr < 32; rr += 4) {
        const int r = base + rr;
        if (r >= NOBS) continue;
        const int i = iobs[r];
        const float mean = p[(size_t)i * 128 + d];
        const float var  = fabsf(p[(size_t)i * 128 + 64 + d]) + 1e-6f;
        const float x    = X[(size_t)r * 64 + d];
        const float m    = M[(size_t)r * 64 + d];
        const float rsv  = rsqrtf(var);
        const float err  = (x - mean) * rsv;
        lacc += 0.5f * (err * err + logf(var)) * m;

        const float* w = sw + d * 64;
        const float* b = sb + d * 16;
        __half2 hv[8];
        #pragma unroll
        for (int j = 0; j < 16; j += 2) {
            float v0 = b[j];
            v0 = fmaf(x, w[j], v0);
            v0 = fmaf(mean, w[16 + j], v0);
            v0 = fmaf(var,  w[32 + j], v0);
            v0 = fmaf(err,  w[48 + j], v0);
            float v1 = b[j + 1];
            v1 = fmaf(x, w[j + 1], v1);
            v1 = fmaf(mean, w[16 + j + 1], v1);
            v1 = fmaf(var,  w[32 + j + 1], v1);
            v1 = fmaf(err,  w[48 + j + 1], v1);
            v0 = fmaxf(v0, 0.0f) * m;
            v1 = fmaxf(v1, 0.0f) * m;
            hv[j >> 1] = __floats2half2_rn(v0, v1);
        }
        uint4* dst = reinterpret_cast<uint4*>(&g_gruin[(size_t)r * K1 + d * 16]);
        dst[0] = *reinterpret_cast<uint4*>(&hv[0]);
        dst[1] = *reinterpret_cast<uint4*>(&hv[4]);
    }

    sred[threadIdx.x] = lacc;
    __syncthreads();
    for (int s = 128; s > 0; s >>= 1) {
        if (threadIdx.x < s) sred[threadIdx.x] += sred[threadIdx.x + s];
        __syncthreads();
    }
    if (threadIdx.x == 0) atomicAdd(&g_loss, sred[0]);
}

// ---------------------------------------------------------------------------
// 3. Gather h[i_obs] -> fp16
// ---------------------------------------------------------------------------
__global__ void gather_h_kernel(const float* __restrict__ h,
                                const int* __restrict__ iobs) {
    const int total = NOBS * (HID / 2);
    int idx = blockIdx.x * blockDim.x + threadIdx.x;
    if (idx >= total) return;
    const int r = idx >> 8;          // HID/2 = 256
    const int c = idx & 255;
    const int i = iobs[r];
    float2 v = *reinterpret_cast<const float2*>(&h[(size_t)i * HID + c * 2]);
    reinterpret_cast<__half2*>(g_hgat)[idx] = __floats2half2_rn(v.x, v.y);
}

// ---------------------------------------------------------------------------
// 4. HMMA GEMM: C[M,1536](fp16) = A[M,K](fp16) @ B[1536,K](fp16)^T
//    BM=128, BN=128, BK=32, 4-stage cp.async multistage
//    (wait(2) -> sync -> prefetch kc+3 -> compute kc),
//    256 thr (8 warps, 4m x 2n), warp tile 32x64, mma.sync m16n8k16,
//    padded 80B smem rows for conflict-free ldmatrix.
// ---------------------------------------------------------------------------
#define STAGES       4
#define STAGE_BYTES  20480          // A 10240 + B 10240
#define SM_B_OFF     10240

__device__ __forceinline__ void load_stage(uint32_t sm, int stage,
                                           const __half* __restrict__ A,
                                           const __half* __restrict__ B,
                                           int m0, int n0, int K, int kc, int tid) {
    const uint32_t base = sm + stage * STAGE_BYTES;
    #pragma unroll
    for (int it = 0; it < 4; it++) {
        const int c = tid + it * 256;           // 0..1023
        const int cc = c & 511;
        const int row = cc >> 2, ch = cc & 3;   // 128 rows x 4 x 16B
        if (c < 512) {  // A
            const int rg = m0 + row;
            const int rc = rg < NOBS ? rg : (NOBS - 1);
            const void* src = A + (size_t)rc * K + kc * 32 + ch * 8;
            cp_async16(base + row * 80 + ch * 16, src, rg < NOBS ? 16 : 0);
        } else {        // B (always in range)
            const void* src = B + (size_t)(n0 + row) * K + kc * 32 + ch * 8;
            cp_async16(base + SM_B_OFF + row * 80 + ch * 16, src, 16);
        }
    }
}

__global__ void __launch_bounds__(256, 2) gemm_hmma_kernel(
    const __half* __restrict__ A, const __half* __restrict__ B,
    __half* __restrict__ C, int K) {
    extern __shared__ __align__(128) char smem[];   // STAGES * STAGE_BYTES
    const uint32_t sm = smem_to_u32(smem);

    const int tid  = threadIdx.x;
    const int lane = tid & 31;
    const int wid  = tid >> 5;
    const int warp_m = wid & 3;     // 4 m-warps, 32 rows each
    const int warp_n = wid >> 2;    // 2 n-warps, 64 cols each

    const int n0 = blockIdx.x * 128;
    const int m0 = blockIdx.y * 128;
    const int nk = K >> 5;

    // per-lane ldmatrix base offsets (bytes) within a stage
    const uint32_t lrow = lane & 15;
    const uint32_t lcol = (lane >> 4) << 4;   // 0 or 16 bytes (8 halfs)
    const uint32_t a_off = (warp_m * 32 + lrow) * 80 + lcol;
    const uint32_t b_off = SM_B_OFF + (warp_n * 64 + lrow) * 80 + lcol;

    float acc[2][8][4];
    #pragma unroll
    for (int mt = 0; mt < 2; mt++)
        #pragma unroll
        for (int nt = 0; nt < 8; nt++)
            #pragma unroll
            for (int e = 0; e < 4; e++) acc[mt][nt][e] = 0.0f;

    // prologue: stages 0..2
    #pragma unroll
    for (int s = 0; s < 3; s++) {
        load_stage(sm, s, A, B, m0, n0, K, s, tid);
        CP_ASYNC_COMMIT();
    }

    for (int kc = 0; kc < nk; kc++) {
        const int buf = kc & 3;
        CP_ASYNC_WAIT_2();          // chunk kc landed (<=2 newer in flight)
        __syncthreads();            // all warps past iteration kc-1's reads

        // prefetch chunk kc+3 into buffer (kc+3)&3 == (kc-1)&3 (just freed)
        if (kc + 3 < nk) load_stage(sm, (kc + 3) & 3, A, B, m0, n0, K, kc + 3, tid);
        CP_ASYNC_COMMIT();          // (possibly empty) group keeps counts exact

        const uint32_t sA = sm + buf * STAGE_BYTES;
        const uint32_t sB = sA;     // b_off already includes SM_B_OFF

        #pragma unroll
        for (int ks = 0; ks < 2; ks++) {
            const uint32_t k0b = ks * 32;      // 16 halfs = 32 bytes
            uint32_t a[2][4];
            LDMATRIX_X4(a[0][0], a[0][1], a[0][2], a[0][3], sA + a_off + k0b);
            LDMATRIX_X4(a[1][0], a[1][1], a[1][2], a[1][3], sA + a_off + 1280 + k0b);
            uint32_t b[8][2];
            #pragma unroll
            for (int nb = 0; nb < 4; nb++) {
                uint32_t r0, r1, r2, r3;
                LDMATRIX_X4(r0, r1, r2, r3, sB + b_off + nb * 1280 + k0b);
                b[2 * nb][0] = r0; b[2 * nb][1] = r2;
                b[2 * nb + 1][0] = r1; b[2 * nb + 1][1] = r3;
            }
            #pragma unroll
            for (int mt = 0; mt < 2; mt++)
                #pragma unroll
                for (int nt = 0; nt < 8; nt++)
                    MMA_16816(acc[mt][nt], a[mt], b[nt]);
        }
        // no trailing sync: next iteration's wait+sync provides the barrier
    }

    // epilogue: fp32 -> fp16, store
    #pragma unroll
    for (int mt = 0; mt < 2; mt++) {
        const int r0 = m0 + warp_m * 32 + mt * 16 + (lane >> 2);
        #pragma unroll
        for (int nt = 0; nt < 8; nt++) {
            const int col = n0 + warp_n * 64 + nt * 8 + (lane & 3) * 2;
            if (r0 < NOBS)
                *reinterpret_cast<__half2*>(&C[(size_t)r0 * H3 + col]) =
                    __floats2half2_rn(acc[mt][nt][0], acc[mt][nt][1]);
            if (r0 + 8 < NOBS)
                *reinterpret_cast<__half2*>(&C[(size_t)(r0 + 8) * H3 + col]) =
                    __floats2half2_rn(acc[mt][nt][2], acc[mt][nt][3]);
        }
    }
}

// ---------------------------------------------------------------------------
// 5. Gate combine + scatter (last occurrence of each index wins)
// ---------------------------------------------------------------------------
__global__ void __launch_bounds__(128) combine_kernel(
    const int* __restrict__ iobs, const float* __restrict__ h,
    const float* __restrict__ bih, const float* __restrict__ bhh,
    float* __restrict__ out) {
    const int r = blockIdx.x;
    const int i = iobs[r];
    if (r + 1 < NOBS && iobs[r + 1] == i) return;   // not last occurrence

    const __half2* gi = reinterpret_cast<const __half2*>(&g_gi[(size_t)r * H3]);
    const __half2* gh = reinterpret_cast<const __half2*>(&g_gh[(size_t)r * H3]);
    const float2* b_ih = reinterpret_cast<const float2*>(bih);
    const float2* b_hh = reinterpret_cast<const float2*>(bhh);
    const float2* hrow = reinterpret_cast<const float2*>(&h[(size_t)i * HID]);
    float2* orow = reinterpret_cast<float2*>(&out[(size_t)i * HID]);

    for (int j = threadIdx.x; j < HID / 2; j += 128) {
        const float2 gir = __half22float2(gi[j]);
        const float2 giz = __half22float2(gi[256 + j]);
        const float2 gin = __half22float2(gi[512 + j]);
        const float2 ghr = __half22float2(gh[j]);
        const float2 ghz = __half22float2(gh[256 + j]);
        const float2 ghn = __half22float2(gh[512 + j]);
        const float2 bir = b_ih[j],       bhr = b_hh[j];
        const float2 biz = b_ih[256 + j], bhz = b_hh[256 + j];
        const float2 bin = b_ih[512 + j], bhn = b_hh[512 + j];
        const float2 hp = hrow[j];

        const float rg0 = 1.0f / (1.0f + expf(-(gir.x + bir.x + ghr.x + bhr.x)));
        const float rg1 = 1.0f / (1.0f + expf(-(gir.y + bir.y + ghr.y + bhr.y)));
        const float zg0 = 1.0f / (1.0f + expf(-(giz.x + biz.x + ghz.x + bhz.x)));
        const float zg1 = 1.0f / (1.0f + expf(-(giz.y + biz.y + ghz.y + bhz.y)));
        const float nn0 = tanhf(gin.x + bin.x + rg0 * (ghn.x + bhn.x));
        const float nn1 = tanhf(gin.y + bin.y + rg1 * (ghn.y + bhn.y));
        float2 o;
        o.x = (1.0f - zg0) * nn0 + zg0 * hp.x;
        o.y = (1.0f - zg1) * nn1 + zg1 * hp.y;
        orow[j] = o;
    }
}

// ---------------------------------------------------------------------------
// 6. Loss store
// ---------------------------------------------------------------------------
__global__ void write_loss_kernel(float* __restrict__ out) {
    out[(size_t)N_ROWS * HID] = g_loss;
}

// ---------------------------------------------------------------------------
// Launch
// ---------------------------------------------------------------------------
extern "C" void kernel_launch(void* const* d_in, const int* in_sizes, int n_in,
                              void* d_out, int out_size) {
    const float* h     = (const float*)d_in[0];
    const float* p     = (const float*)d_in[1];
    const float* X     = (const float*)d_in[2];
    const float* M     = (const float*)d_in[3];
    const int*   iobs  = (const int*)  d_in[4];
    const float* wprep = (const float*)d_in[5];
    const float* bprep = (const float*)d_in[6];
    const float* wih   = (const float*)d_in[7];
    const float* whh   = (const float*)d_in[8];
    const float* bih   = (const float*)d_in[9];
    const float* bhh   = (const float*)d_in[10];
    float* out = (float*)d_out;

    cudaFuncSetAttribute(gemm_hmma_kernel,
                         cudaFuncAttributeMaxDynamicSharedMemorySize,
                         STAGES * STAGE_BYTES);

    // 1. convert weights to fp16, zero loss accumulator
    convert_weights_kernel<<<512, 256>>>(wih, whh);

    // 2. out[:N*HID] = h
    cudaMemcpyAsync(out, h, (size_t)N_ROWS * HID * sizeof(float),
                    cudaMemcpyDeviceToDevice);

    // 3. prep: loss + gru_in (fp16)
    prep_kernel<<<(NOBS + 31) / 32, 256>>>(p, X, M, iobs, wprep, bprep);

    // 4. gather h[i_obs] -> fp16
    gather_h_kernel<<<(NOBS * (HID / 2) + 255) / 256, 256>>>(h, iobs);

    // device pointers to the scratch symbols for GEMM args
    __half *d_gruin, *d_hgat, *d_gi, *d_gh, *d_wih, *d_whh;
    cudaGetSymbolAddress((void**)&d_gruin, g_gruin);
    cudaGetSymbolAddress((void**)&d_hgat,  g_hgat);
    cudaGetSymbolAddress((void**)&d_gi,    g_gi);
    cudaGetSymbolAddress((void**)&d_gh,    g_gh);
    cudaGetSymbolAddress((void**)&d_wih,   g_Wih_h);
    cudaGetSymbolAddress((void**)&d_whh,   g_Whh_h);

    // 5. gi = gru_in @ Wih^T   (M=50000, N=1536, K=1024)
    gemm_hmma_kernel<<<dim3(12, MTILES), 256, STAGES * STAGE_BYTES>>>(
        d_gruin, d_wih, d_gi, K1);

    // 6. gh = h_gat @ Whh^T    (M=50000, N=1536, K=512)
    gemm_hmma_kernel<<<dim3(12, MTILES), 256, STAGES * STAGE_BYTES>>>(
        d_hgat, d_whh, d_gh, K2);

    // 7. gates + scatter (last-wins)
    combine_kernel<<<NOBS, 128>>>(iobs, h, bih, bhh, out);

    // 8. loss
    if (out_size > N_ROWS * HID)
        write_loss_kernel<<<1, 1>>>(out);
}